// round 4
// baseline (speedup 1.0000x reference)
#include <cuda_runtime.h>
#include <math.h>

#define B 64
#define C 256
#define H 56
#define W 56
#define HW 3136
#define HW4 784          // HW / 4
#define D 16
#define TOPK 38
#define HALF 2
#define NROWS (B * C)          // 16384
#define BLKS_PER_S (C + TOPK)  // 294
#define NBLKS (B * BLKS_PER_S) // 18816

// Scratch (device globals — no allocation allowed)
__device__ float g_pooled[NROWS];
__device__ int   g_amax[NROWS];
__device__ int   g_cnt[B];      // reset to 0 each launch via memset node

__device__ __forceinline__ int ld_acquire(const int* p) {
    int v;
    asm volatile("ld.acquire.gpu.s32 %0, [%1];" : "=r"(v) : "l"(p));
    return v;
}

// ---------------------------------------------------------------------------
// Fused kernel. Per sample s: 256 producer blocks (pool+argmax+copy for one
// row), then 38 apply blocks (wait for sample, SE+rank, drop-box one row).
// Apply blocks only wait on lower-blockIdx blocks -> dispatch order guarantees
// forward progress.
// ---------------------------------------------------------------------------
__global__ __launch_bounds__(256) void fused_targetdrop(
    const float4* __restrict__ x, float4* __restrict__ out,
    const float* __restrict__ w1, const float* __restrict__ w2)
{
    const int s = blockIdx.x / BLKS_PER_S;
    const int r = blockIdx.x % BLKS_PER_S;
    const int t = threadIdx.x;

    __shared__ float sv[8], ss[8];
    __shared__ int   si[8];
    __shared__ float p[C];
    __shared__ float h[D];
    __shared__ float m[C];
    __shared__ int   selc;

    if (r < C) {
        // ================= PRODUCER: row = s*C + r =================
        const int row = s * C + r;
        const float4* __restrict__ xr = x + (size_t)row * HW4;
        float4* __restrict__ orow = out + (size_t)row * HW4;
        const bool tail = (t < 16);

        float4 v0 = xr[t];
        float4 v1 = xr[t + 256];
        float4 v2 = xr[t + 512];
        float4 v3;
        if (tail) v3 = xr[t + 768];

        __stcs(orow + t,       v0);
        __stcs(orow + t + 256, v1);
        __stcs(orow + t + 512, v2);
        if (tail) __stcs(orow + t + 768, v3);

        float sum = ((v0.x + v0.y) + (v0.z + v0.w))
                  + ((v1.x + v1.y) + (v1.z + v1.w))
                  + ((v2.x + v2.y) + (v2.z + v2.w));
        if (tail) sum += ((v3.x + v3.y) + (v3.z + v3.w));

        float bv = v0.x; int bi = (t << 2);
        if (v0.y > bv) { bv = v0.y; bi = (t << 2) + 1; }
        if (v0.z > bv) { bv = v0.z; bi = (t << 2) + 2; }
        if (v0.w > bv) { bv = v0.w; bi = (t << 2) + 3; }
        {
            const int b1 = ((t + 256) << 2);
            if (v1.x > bv) { bv = v1.x; bi = b1; }
            if (v1.y > bv) { bv = v1.y; bi = b1 + 1; }
            if (v1.z > bv) { bv = v1.z; bi = b1 + 2; }
            if (v1.w > bv) { bv = v1.w; bi = b1 + 3; }
            const int b2 = ((t + 512) << 2);
            if (v2.x > bv) { bv = v2.x; bi = b2; }
            if (v2.y > bv) { bv = v2.y; bi = b2 + 1; }
            if (v2.z > bv) { bv = v2.z; bi = b2 + 2; }
            if (v2.w > bv) { bv = v2.w; bi = b2 + 3; }
        }
        if (tail) {
            const int b3 = ((t + 768) << 2);
            if (v3.x > bv) { bv = v3.x; bi = b3; }
            if (v3.y > bv) { bv = v3.y; bi = b3 + 1; }
            if (v3.z > bv) { bv = v3.z; bi = b3 + 2; }
            if (v3.w > bv) { bv = v3.w; bi = b3 + 3; }
        }

        #pragma unroll
        for (int o = 16; o > 0; o >>= 1) {
            float ov = __shfl_down_sync(0xFFFFFFFFu, bv, o);
            int   oi = __shfl_down_sync(0xFFFFFFFFu, bi, o);
            float os = __shfl_down_sync(0xFFFFFFFFu, sum, o);
            sum += os;
            if (ov > bv || (ov == bv && oi < bi)) { bv = ov; bi = oi; }
        }

        const int w = t >> 5, l = t & 31;
        if (l == 0) { sv[w] = bv; si[w] = bi; ss[w] = sum; }
        __syncthreads();
        if (t == 0) {
            float fbv = sv[0]; int fbi = si[0]; float fs = ss[0];
            #pragma unroll
            for (int j = 1; j < 8; j++) {
                fs += ss[j];
                if (sv[j] > fbv || (sv[j] == fbv && si[j] < fbi)) { fbv = sv[j]; fbi = si[j]; }
            }
            g_pooled[row] = fs * (1.0f / (float)HW);
            g_amax[row]   = fbi;
            __threadfence();                 // release stats before signaling
            atomicAdd(&g_cnt[s], 1);
        }
    } else {
        // ================= APPLY: sample s, target rank r-C =================
        const int rank_target = r - C;

        if (t == 0) {
            while (ld_acquire(&g_cnt[s]) < C) __nanosleep(128);
        }
        __syncthreads();
        __threadfence();

        // ---- SE module (identical arithmetic to validated k2) ----
        const int c = t;
        p[c] = g_pooled[s * C + c];
        __syncthreads();
        {
            const int d = c >> 4, g = c & 15;
            float a = 0.0f;
            #pragma unroll
            for (int j = 0; j < 16; j++) {
                const int cc = g * 16 + j;
                a = fmaf(p[cc], __ldg(&w1[d * C + cc]), a);
            }
            #pragma unroll
            for (int o = 8; o > 0; o >>= 1) a += __shfl_xor_sync(0xFFFFFFFFu, a, o);
            if (g == 0) h[d] = fmaxf(a, 0.0f);
        }
        __syncthreads();

        float z = 0.0f;
        const float* w2r = w2 + c * D;
        #pragma unroll
        for (int d = 0; d < D; d++) z = fmaf(h[d], __ldg(&w2r[d]), z);
        m[c] = 1.0f / (1.0f + expf(-z));
        __syncthreads();

        const float mc = m[c];
        int rank = 0;
        #pragma unroll 8
        for (int j = 0; j < C; j++) {
            const float mj = m[j];
            rank += (mj > mc) || (mj == mc && j < c);
        }
        if (rank == rank_target) selc = c;   // ranks are a permutation: unique writer
        __syncthreads();

        // ---- Apply drop-box to row (s, selc) ----
        const int row = s * C + selc;
        const int mi = g_amax[row];
        const int mh = mi / W, mw = mi % W;
        const int h1 = max(mh - HALF, 0), h2 = min(mh + HALF, H - 1);
        const int wl = max(mw - HALF, 0), wr = min(mw + HALF, W - 1);
        const float lam = (float)HW / ((float)HW - (float)((h2 - h1 + 1) * (wr - wl + 1)));

        const float4* __restrict__ xr = x + (size_t)row * HW4;
        float4* __restrict__ orow = out + (size_t)row * HW4;
        const bool tail = (t < 16);

        float4 v0 = xr[t];
        float4 v1 = xr[t + 256];
        float4 v2 = xr[t + 512];
        float4 v3;
        if (tail) v3 = xr[t + 768];

        #define APPLY(v, i4) {                                                \
            const int e  = (i4) << 2;                                         \
            const int hh = e / W;                                             \
            const int ww = e - hh * W;                                        \
            const bool hin = (hh >= h1) & (hh <= h2);                         \
            float4 rr;                                                        \
            rr.x = (hin & (ww     >= wl) & (ww     <= wr)) ? 0.0f : v.x * lam; \
            rr.y = (hin & (ww + 1 >= wl) & (ww + 1 <= wr)) ? 0.0f : v.y * lam; \
            rr.z = (hin & (ww + 2 >= wl) & (ww + 2 <= wr)) ? 0.0f : v.z * lam; \
            rr.w = (hin & (ww + 3 >= wl) & (ww + 3 <= wr)) ? 0.0f : v.w * lam; \
            __stcs(orow + (i4), rr);                                          \
        }

        APPLY(v0, t);
        APPLY(v1, t + 256);
        APPLY(v2, t + 512);
        if (tail) APPLY(v3, t + 768);
        #undef APPLY
    }
}

// ---------------------------------------------------------------------------
extern "C" void kernel_launch(void* const* d_in, const int* in_sizes, int n_in,
                              void* d_out, int out_size)
{
    const float4* x  = (const float4*)d_in[0];
    const float*  w1 = (const float*)d_in[1];
    const float*  w2 = (const float*)d_in[2];
    float4* out = (float4*)d_out;

    // Reset per-sample arrival counters (captured as a memset node).
    void* cnt_ptr = nullptr;
    cudaGetSymbolAddress(&cnt_ptr, g_cnt);
    cudaMemsetAsync(cnt_ptr, 0, B * sizeof(int), 0);

    fused_targetdrop<<<NBLKS, 256>>>(x, out, w1, w2);
}

// round 9
// speedup vs baseline: 1.2054x; 1.2054x over previous
#include <cuda_runtime.h>
#include <math.h>

#define B 64
#define C 256
#define H 56
#define W 56
#define HW 3136
#define HW4 784          // HW / 4
#define D 16
#define TOPK 38
#define HALF 2
#define NROWS (B * C)    // 16384
#define NSEL (B * TOPK)  // 2432

// Scratch (device globals — no allocation allowed)
__device__ float g_pooled[NROWS];
__device__ int   g_amax[NROWS];

// ---------------------------------------------------------------------------
// Kernel 1: per-(b,c) plane — copy x -> out (evict-first stores),
// compute mean and argmax. One block (256 threads) per row (784 float4).
// (unchanged from the validated 57.2us version)
// ---------------------------------------------------------------------------
__global__ __launch_bounds__(256) void k1_pool_amax_copy(
    const float4* __restrict__ x, float4* __restrict__ out)
{
    const int row = blockIdx.x;
    const float4* __restrict__ xr = x + (size_t)row * HW4;
    float4* __restrict__ orow = out + (size_t)row * HW4;
    const int t = threadIdx.x;
    const bool tail = (t < 16);

    float4 v0 = xr[t];
    float4 v1 = xr[t + 256];
    float4 v2 = xr[t + 512];
    float4 v3;
    if (tail) v3 = xr[t + 768];

    __stcs(orow + t,       v0);
    __stcs(orow + t + 256, v1);
    __stcs(orow + t + 512, v2);
    if (tail) __stcs(orow + t + 768, v3);

    float s = ((v0.x + v0.y) + (v0.z + v0.w))
            + ((v1.x + v1.y) + (v1.z + v1.w))
            + ((v2.x + v2.y) + (v2.z + v2.w));
    if (tail) s += ((v3.x + v3.y) + (v3.z + v3.w));

    float bv = v0.x; int bi = (t << 2);
    if (v0.y > bv) { bv = v0.y; bi = (t << 2) + 1; }
    if (v0.z > bv) { bv = v0.z; bi = (t << 2) + 2; }
    if (v0.w > bv) { bv = v0.w; bi = (t << 2) + 3; }
    {
        const int b1 = ((t + 256) << 2);
        if (v1.x > bv) { bv = v1.x; bi = b1; }
        if (v1.y > bv) { bv = v1.y; bi = b1 + 1; }
        if (v1.z > bv) { bv = v1.z; bi = b1 + 2; }
        if (v1.w > bv) { bv = v1.w; bi = b1 + 3; }
        const int b2 = ((t + 512) << 2);
        if (v2.x > bv) { bv = v2.x; bi = b2; }
        if (v2.y > bv) { bv = v2.y; bi = b2 + 1; }
        if (v2.z > bv) { bv = v2.z; bi = b2 + 2; }
        if (v2.w > bv) { bv = v2.w; bi = b2 + 3; }
    }
    if (tail) {
        const int b3 = ((t + 768) << 2);
        if (v3.x > bv) { bv = v3.x; bi = b3; }
        if (v3.y > bv) { bv = v3.y; bi = b3 + 1; }
        if (v3.z > bv) { bv = v3.z; bi = b3 + 2; }
        if (v3.w > bv) { bv = v3.w; bi = b3 + 3; }
    }

    #pragma unroll
    for (int o = 16; o > 0; o >>= 1) {
        float ov = __shfl_down_sync(0xFFFFFFFFu, bv, o);
        int   oi = __shfl_down_sync(0xFFFFFFFFu, bi, o);
        float os = __shfl_down_sync(0xFFFFFFFFu, s,  o);
        s += os;
        if (ov > bv || (ov == bv && oi < bi)) { bv = ov; bi = oi; }
    }

    __shared__ float sv[8], ss[8];
    __shared__ int   si[8];
    const int w = t >> 5, l = t & 31;
    if (l == 0) { sv[w] = bv; si[w] = bi; ss[w] = s; }
    __syncthreads();
    if (t == 0) {
        float fbv = sv[0]; int fbi = si[0]; float fs = ss[0];
        #pragma unroll
        for (int j = 1; j < 8; j++) {
            fs += ss[j];
            if (sv[j] > fbv || (sv[j] == fbv && si[j] < fbi)) { fbv = sv[j]; fbi = si[j]; }
        }
        g_pooled[row] = fs * (1.0f / (float)HW);
        g_amax[row]   = fbi;
    }
}

// ---------------------------------------------------------------------------
// Kernel 2: merged SE + top-k + apply. One block per (sample, rank):
// grid = 64*38. Each block redundantly computes the SE module for its
// sample (inputs L2-hot), finds the channel whose rank == its target,
// and rewrites that row with the drop-box mask.
// ---------------------------------------------------------------------------
__global__ __launch_bounds__(256) void k2_se_apply(
    const float4* __restrict__ x, float4* __restrict__ out,
    const float* __restrict__ w1, const float* __restrict__ w2)
{
    const int s = blockIdx.x / TOPK;
    const int rank_target = blockIdx.x % TOPK;
    const int t = threadIdx.x;
    const int c = t;

    __shared__ float p[C];
    __shared__ float h[D];
    __shared__ float m[C];
    __shared__ int   selc;

    p[c] = g_pooled[s * C + c];
    __syncthreads();

    // hidden[d]: 16 threads per d, 16-lane shfl segment reduce
    {
        const int d = c >> 4, g = c & 15;
        float a = 0.0f;
        #pragma unroll
        for (int j = 0; j < 16; j++) {
            const int cc = g * 16 + j;
            a = fmaf(p[cc], __ldg(&w1[d * C + cc]), a);
        }
        #pragma unroll
        for (int o = 8; o > 0; o >>= 1) a += __shfl_xor_sync(0xFFFFFFFFu, a, o);
        if (g == 0) h[d] = fmaxf(a, 0.0f);
    }
    __syncthreads();

    float z = 0.0f;
    const float* w2r = w2 + c * D;
    #pragma unroll
    for (int d = 0; d < D; d++) z = fmaf(h[d], __ldg(&w2r[d]), z);
    m[c] = 1.0f / (1.0f + expf(-z));
    __syncthreads();

    const float mc = m[c];
    int rank = 0;
    #pragma unroll 8
    for (int j = 0; j < C; j++) {
        const float mj = m[j];
        rank += (mj > mc) || (mj == mc && j < c);
    }
    if (rank == rank_target) selc = c;    // ranks are a permutation: unique writer
    __syncthreads();

    // ---- Apply drop-box to row (s, selc) ----
    const int row = s * C + selc;
    const int mi = g_amax[row];
    const int mh = mi / W, mw = mi % W;
    const int h1 = max(mh - HALF, 0), h2 = min(mh + HALF, H - 1);
    const int wl = max(mw - HALF, 0), wr = min(mw + HALF, W - 1);
    const float lam = (float)HW / ((float)HW - (float)((h2 - h1 + 1) * (wr - wl + 1)));

    const float4* __restrict__ xr = x + (size_t)row * HW4;
    float4* __restrict__ orow = out + (size_t)row * HW4;
    const bool tail = (t < 16);

    float4 v0 = xr[t];
    float4 v1 = xr[t + 256];
    float4 v2 = xr[t + 512];
    float4 v3;
    if (tail) v3 = xr[t + 768];

    #define APPLY(v, i4) {                                                \
        const int e  = (i4) << 2;                                         \
        const int hh = e / W;                                             \
        const int ww = e - hh * W;                                        \
        const bool hin = (hh >= h1) & (hh <= h2);                         \
        float4 rr;                                                        \
        rr.x = (hin & (ww     >= wl) & (ww     <= wr)) ? 0.0f : v.x * lam; \
        rr.y = (hin & (ww + 1 >= wl) & (ww + 1 <= wr)) ? 0.0f : v.y * lam; \
        rr.z = (hin & (ww + 2 >= wl) & (ww + 2 <= wr)) ? 0.0f : v.z * lam; \
        rr.w = (hin & (ww + 3 >= wl) & (ww + 3 <= wr)) ? 0.0f : v.w * lam; \
        __stcs(orow + (i4), rr);                                          \
    }

    APPLY(v0, t);
    APPLY(v1, t + 256);
    APPLY(v2, t + 512);
    if (tail) APPLY(v3, t + 768);
    #undef APPLY
}

// ---------------------------------------------------------------------------
extern "C" void kernel_launch(void* const* d_in, const int* in_sizes, int n_in,
                              void* d_out, int out_size)
{
    const float4* x  = (const float4*)d_in[0];
    const float*  w1 = (const float*)d_in[1];
    const float*  w2 = (const float*)d_in[2];
    float4* out = (float4*)d_out;

    k1_pool_amax_copy<<<NROWS, 256>>>(x, out);
    k2_se_apply<<<NSEL, 256>>>(x, out, w1, w2);
}

// round 10
// speedup vs baseline: 1.4277x; 1.1844x over previous
#include <cuda_runtime.h>
#include <math.h>

#define B 64
#define C 256
#define H 56
#define W 56
#define HW 3136
#define HW4 784          // HW / 4
#define D 16
#define TOPK 38
#define HALF 2
#define NROWS (B * C)    // 16384
#define NSEL (B * TOPK)  // 2432

// Scratch (device globals — no allocation allowed)
__device__ float g_pooled[NROWS];
__device__ int   g_amax[NROWS];

// ---------------------------------------------------------------------------
// Kernel 1: per-(b,c) plane — copy x -> out (evict-first stores),
// compute mean and argmax. One block (256 threads) per row (784 float4).
// (unchanged from the validated 57.2us version)
// ---------------------------------------------------------------------------
__global__ __launch_bounds__(256) void k1_pool_amax_copy(
    const float4* __restrict__ x, float4* __restrict__ out)
{
    const int row = blockIdx.x;
    const float4* __restrict__ xr = x + (size_t)row * HW4;
    float4* __restrict__ orow = out + (size_t)row * HW4;
    const int t = threadIdx.x;
    const bool tail = (t < 16);

    float4 v0 = xr[t];
    float4 v1 = xr[t + 256];
    float4 v2 = xr[t + 512];
    float4 v3;
    if (tail) v3 = xr[t + 768];

    __stcs(orow + t,       v0);
    __stcs(orow + t + 256, v1);
    __stcs(orow + t + 512, v2);
    if (tail) __stcs(orow + t + 768, v3);

    float s = ((v0.x + v0.y) + (v0.z + v0.w))
            + ((v1.x + v1.y) + (v1.z + v1.w))
            + ((v2.x + v2.y) + (v2.z + v2.w));
    if (tail) s += ((v3.x + v3.y) + (v3.z + v3.w));

    float bv = v0.x; int bi = (t << 2);
    if (v0.y > bv) { bv = v0.y; bi = (t << 2) + 1; }
    if (v0.z > bv) { bv = v0.z; bi = (t << 2) + 2; }
    if (v0.w > bv) { bv = v0.w; bi = (t << 2) + 3; }
    {
        const int b1 = ((t + 256) << 2);
        if (v1.x > bv) { bv = v1.x; bi = b1; }
        if (v1.y > bv) { bv = v1.y; bi = b1 + 1; }
        if (v1.z > bv) { bv = v1.z; bi = b1 + 2; }
        if (v1.w > bv) { bv = v1.w; bi = b1 + 3; }
        const int b2 = ((t + 512) << 2);
        if (v2.x > bv) { bv = v2.x; bi = b2; }
        if (v2.y > bv) { bv = v2.y; bi = b2 + 1; }
        if (v2.z > bv) { bv = v2.z; bi = b2 + 2; }
        if (v2.w > bv) { bv = v2.w; bi = b2 + 3; }
    }
    if (tail) {
        const int b3 = ((t + 768) << 2);
        if (v3.x > bv) { bv = v3.x; bi = b3; }
        if (v3.y > bv) { bv = v3.y; bi = b3 + 1; }
        if (v3.z > bv) { bv = v3.z; bi = b3 + 2; }
        if (v3.w > bv) { bv = v3.w; bi = b3 + 3; }
    }

    #pragma unroll
    for (int o = 16; o > 0; o >>= 1) {
        float ov = __shfl_down_sync(0xFFFFFFFFu, bv, o);
        int   oi = __shfl_down_sync(0xFFFFFFFFu, bi, o);
        float os = __shfl_down_sync(0xFFFFFFFFu, s,  o);
        s += os;
        if (ov > bv || (ov == bv && oi < bi)) { bv = ov; bi = oi; }
    }

    __shared__ float sv[8], ss[8];
    __shared__ int   si[8];
    const int w = t >> 5, l = t & 31;
    if (l == 0) { sv[w] = bv; si[w] = bi; ss[w] = s; }
    __syncthreads();
    if (t == 0) {
        float fbv = sv[0]; int fbi = si[0]; float fs = ss[0];
        #pragma unroll
        for (int j = 1; j < 8; j++) {
            fs += ss[j];
            if (sv[j] > fbv || (sv[j] == fbv && si[j] < fbi)) { fbv = sv[j]; fbi = si[j]; }
        }
        g_pooled[row] = fs * (1.0f / (float)HW);
        g_amax[row]   = fbi;
    }
}

// ---------------------------------------------------------------------------
// Kernel 2: merged SE + top-k + apply. One block per (sample, rank).
// All weight accesses coalesced: w1 read coalesced from global (L2-hot),
// w2 staged TRANSPOSED into smem so the z computation is conflict-free.
// ---------------------------------------------------------------------------
__global__ __launch_bounds__(256) void k2_se_apply(
    const float4* __restrict__ x, float4* __restrict__ out,
    const float* __restrict__ w1, const float4* __restrict__ w2v)
{
    const int s = blockIdx.x / TOPK;
    const int rank_target = blockIdx.x % TOPK;
    const int t = threadIdx.x;
    const int c = t;
    const int lane = t & 31, warp = t >> 5;

    __shared__ float p[C];
    __shared__ float w2t[D * C];   // transposed: w2t[d*C + c] = w2[c*D + d]
    __shared__ float h[D];
    __shared__ float m[C];
    __shared__ int   selc;

    // Stage pooled (coalesced) and w2 transposed (coalesced load, scatter STS)
    p[c] = g_pooled[s * C + c];
    #pragma unroll
    for (int i = 0; i < 4; i++) {
        const int idx = c + i * 256;          // float4 index into w2 (4096 floats)
        const float4 v = w2v[idx];
        const int e = idx << 2;               // element index = ch*16 + d
        const int ch = e >> 4;
        const int d0 = e & 15;
        w2t[(d0    ) * C + ch] = v.x;
        w2t[(d0 + 1) * C + ch] = v.y;
        w2t[(d0 + 2) * C + ch] = v.z;
        w2t[(d0 + 3) * C + ch] = v.w;
    }
    __syncthreads();

    // hidden: warp w computes d = 2w and 2w+1; lanes read w1 coalesced.
    {
        const int d0 = warp * 2;
        float a0 = 0.0f, a1 = 0.0f;
        #pragma unroll
        for (int k = 0; k < 8; k++) {
            const int cc = lane + 32 * k;
            const float pv = p[cc];
            a0 = fmaf(pv, __ldg(&w1[(d0    ) * C + cc]), a0);
            a1 = fmaf(pv, __ldg(&w1[(d0 + 1) * C + cc]), a1);
        }
        #pragma unroll
        for (int o = 16; o > 0; o >>= 1) {
            a0 += __shfl_xor_sync(0xFFFFFFFFu, a0, o);
            a1 += __shfl_xor_sync(0xFFFFFFFFu, a1, o);
        }
        if (lane == 0) { h[d0] = fmaxf(a0, 0.0f); h[d0 + 1] = fmaxf(a1, 0.0f); }
    }
    __syncthreads();

    // z[c]: conflict-free smem reads (consecutive lanes -> consecutive banks)
    float z = 0.0f;
    #pragma unroll
    for (int d = 0; d < D; d++) z = fmaf(h[d], w2t[d * C + c], z);
    m[c] = 1.0f / (1.0f + expf(-z));
    __syncthreads();

    // Rank of channel c within sample (first-index tie-break)
    const float mc = m[c];
    int rank = 0;
    #pragma unroll 8
    for (int j = 0; j < C; j++) {
        const float mj = m[j];
        rank += (mj > mc) || (mj == mc && j < c);
    }
    if (rank == rank_target) selc = c;    // ranks are a permutation: unique writer
    __syncthreads();

    // ---- Apply drop-box to row (s, selc) ----
    const int row = s * C + selc;
    const int mi = g_amax[row];
    const int mh = mi / W, mw = mi % W;
    const int h1 = max(mh - HALF, 0), h2 = min(mh + HALF, H - 1);
    const int wl = max(mw - HALF, 0), wr = min(mw + HALF, W - 1);
    const float lam = (float)HW / ((float)HW - (float)((h2 - h1 + 1) * (wr - wl + 1)));

    const float4* __restrict__ xr = x + (size_t)row * HW4;
    float4* __restrict__ orow = out + (size_t)row * HW4;
    const bool tail = (t < 16);

    float4 v0 = xr[t];
    float4 v1 = xr[t + 256];
    float4 v2 = xr[t + 512];
    float4 v3;
    if (tail) v3 = xr[t + 768];

    #define APPLY(v, i4) {                                                \
        const int e  = (i4) << 2;                                         \
        const int hh = e / W;                                             \
        const int ww = e - hh * W;                                        \
        const bool hin = (hh >= h1) & (hh <= h2);                         \
        float4 rr;                                                        \
        rr.x = (hin & (ww     >= wl) & (ww     <= wr)) ? 0.0f : v.x * lam; \
        rr.y = (hin & (ww + 1 >= wl) & (ww + 1 <= wr)) ? 0.0f : v.y * lam; \
        rr.z = (hin & (ww + 2 >= wl) & (ww + 2 <= wr)) ? 0.0f : v.z * lam; \
        rr.w = (hin & (ww + 3 >= wl) & (ww + 3 <= wr)) ? 0.0f : v.w * lam; \
        __stcs(orow + (i4), rr);                                          \
    }

    APPLY(v0, t);
    APPLY(v1, t + 256);
    APPLY(v2, t + 512);
    if (tail) APPLY(v3, t + 768);
    #undef APPLY
}

// ---------------------------------------------------------------------------
extern "C" void kernel_launch(void* const* d_in, const int* in_sizes, int n_in,
                              void* d_out, int out_size)
{
    const float4* x  = (const float4*)d_in[0];
    const float*  w1 = (const float*)d_in[1];
    const float4* w2 = (const float4*)d_in[2];
    float4* out = (float4*)d_out;

    k1_pool_amax_copy<<<NROWS, 256>>>(x, out);
    k2_se_apply<<<NSEL, 256>>>(x, out, w1, w2);
}

// round 11
// speedup vs baseline: 1.5965x; 1.1182x over previous
#include <cuda_runtime.h>
#include <math.h>

#define B 64
#define C 256
#define H 56
#define W 56
#define HW 3136
#define HW4 784          // HW / 4
#define D 16
#define TOPK 38
#define HALF 2
#define NROWS (B * C)    // 16384
#define NSEL (B * TOPK)  // 2432

// Scratch (device globals — no allocation allowed)
__device__ float g_pooled[NROWS];
__device__ int   g_amax[NROWS];
__device__ int   g_sel[NSEL];   // packed: (row << 12) | argmax_idx
__device__ int   g_cnt[B];      // reset each launch via memset node

// ---------------------------------------------------------------------------
// Kernel 1: per-(b,c) plane — copy x -> out (evict-first stores), mean +
// argmax (validated 57.2us body). The LAST-ARRIVING block of each sample
// additionally computes the SE module + top-k ranks for that sample and
// writes packed g_sel. No spinning: exactly one block takes the branch.
// ---------------------------------------------------------------------------
__global__ __launch_bounds__(256) void k1_pool_amax_copy_se(
    const float4* __restrict__ x, float4* __restrict__ out,
    const float* __restrict__ w1, const float* __restrict__ w2)
{
    const int row = blockIdx.x;
    const int s   = row >> 8;            // sample = row / C
    const float4* __restrict__ xr = x + (size_t)row * HW4;
    float4* __restrict__ orow = out + (size_t)row * HW4;
    const int t = threadIdx.x;
    const bool tail = (t < 16);

    float4 v0 = xr[t];
    float4 v1 = xr[t + 256];
    float4 v2 = xr[t + 512];
    float4 v3;
    if (tail) v3 = xr[t + 768];

    __stcs(orow + t,       v0);
    __stcs(orow + t + 256, v1);
    __stcs(orow + t + 512, v2);
    if (tail) __stcs(orow + t + 768, v3);

    float sum = ((v0.x + v0.y) + (v0.z + v0.w))
              + ((v1.x + v1.y) + (v1.z + v1.w))
              + ((v2.x + v2.y) + (v2.z + v2.w));
    if (tail) sum += ((v3.x + v3.y) + (v3.z + v3.w));

    float bv = v0.x; int bi = (t << 2);
    if (v0.y > bv) { bv = v0.y; bi = (t << 2) + 1; }
    if (v0.z > bv) { bv = v0.z; bi = (t << 2) + 2; }
    if (v0.w > bv) { bv = v0.w; bi = (t << 2) + 3; }
    {
        const int b1 = ((t + 256) << 2);
        if (v1.x > bv) { bv = v1.x; bi = b1; }
        if (v1.y > bv) { bv = v1.y; bi = b1 + 1; }
        if (v1.z > bv) { bv = v1.z; bi = b1 + 2; }
        if (v1.w > bv) { bv = v1.w; bi = b1 + 3; }
        const int b2 = ((t + 512) << 2);
        if (v2.x > bv) { bv = v2.x; bi = b2; }
        if (v2.y > bv) { bv = v2.y; bi = b2 + 1; }
        if (v2.z > bv) { bv = v2.z; bi = b2 + 2; }
        if (v2.w > bv) { bv = v2.w; bi = b2 + 3; }
    }
    if (tail) {
        const int b3 = ((t + 768) << 2);
        if (v3.x > bv) { bv = v3.x; bi = b3; }
        if (v3.y > bv) { bv = v3.y; bi = b3 + 1; }
        if (v3.z > bv) { bv = v3.z; bi = b3 + 2; }
        if (v3.w > bv) { bv = v3.w; bi = b3 + 3; }
    }

    #pragma unroll
    for (int o = 16; o > 0; o >>= 1) {
        float ov = __shfl_down_sync(0xFFFFFFFFu, bv, o);
        int   oi = __shfl_down_sync(0xFFFFFFFFu, bi, o);
        float os = __shfl_down_sync(0xFFFFFFFFu, sum, o);
        sum += os;
        if (ov > bv || (ov == bv && oi < bi)) { bv = ov; bi = oi; }
    }

    __shared__ float sv[8], ss[8];
    __shared__ int   si[8];
    __shared__ int   is_last;
    const int w = t >> 5, l = t & 31;
    if (l == 0) { sv[w] = bv; si[w] = bi; ss[w] = sum; }
    __syncthreads();
    if (t == 0) {
        float fbv = sv[0]; int fbi = si[0]; float fs = ss[0];
        #pragma unroll
        for (int j = 1; j < 8; j++) {
            fs += ss[j];
            if (sv[j] > fbv || (sv[j] == fbv && si[j] < fbi)) { fbv = sv[j]; fbi = si[j]; }
        }
        g_pooled[row] = fs * (1.0f / (float)HW);
        g_amax[row]   = fbi;
        __threadfence();                       // release stats
        is_last = (atomicAdd(&g_cnt[s], 1) == C - 1);
    }
    __syncthreads();

    if (!is_last) return;

    // ============ SE + top-k for sample s (exactly one block) ============
    __threadfence();                           // acquire: other blocks' stats
    __shared__ float p[C];
    __shared__ float h[D];
    __shared__ float m[C];

    const int c = t;
    p[c] = g_pooled[s * C + c];
    __syncthreads();

    // hidden: warp w computes d = 2w, 2w+1; coalesced w1 reads
    {
        const int d0 = w * 2;
        float a0 = 0.0f, a1 = 0.0f;
        #pragma unroll
        for (int k = 0; k < 8; k++) {
            const int cc = l + 32 * k;
            const float pv = p[cc];
            a0 = fmaf(pv, __ldg(&w1[(d0    ) * C + cc]), a0);
            a1 = fmaf(pv, __ldg(&w1[(d0 + 1) * C + cc]), a1);
        }
        #pragma unroll
        for (int o = 16; o > 0; o >>= 1) {
            a0 += __shfl_xor_sync(0xFFFFFFFFu, a0, o);
            a1 += __shfl_xor_sync(0xFFFFFFFFu, a1, o);
        }
        if (l == 0) { h[d0] = fmaxf(a0, 0.0f); h[d0 + 1] = fmaxf(a1, 0.0f); }
    }
    __syncthreads();

    // z[c]: 16 scattered w2 loads — only 64 blocks ever run this, cost tiny
    float z = 0.0f;
    #pragma unroll
    for (int d = 0; d < D; d++) z = fmaf(h[d], __ldg(&w2[c * D + d]), z);
    m[c] = 1.0f / (1.0f + expf(-z));
    __syncthreads();

    const float mc = m[c];
    int rank = 0;
    #pragma unroll 8
    for (int j = 0; j < C; j++) {
        const float mj = m[j];
        rank += (mj > mc) || (mj == mc && j < c);
    }
    if (rank < TOPK) {
        const int rc = s * C + c;
        g_sel[s * TOPK + rank] = (rc << 12) | g_amax[rc];
    }
}

// ---------------------------------------------------------------------------
// Kernel 2: rewrite the 2432 selected rows with the drop-box mask.
// One block per selected row; single dependent load for (row, argmax).
// ---------------------------------------------------------------------------
__global__ __launch_bounds__(256) void k3_apply(
    const float4* __restrict__ x, float4* __restrict__ out)
{
    const int packed = g_sel[blockIdx.x];
    const int row = packed >> 12;
    const int mi  = packed & 0xFFF;
    const int mh = mi / W, mw = mi % W;
    const int h1 = max(mh - HALF, 0), h2 = min(mh + HALF, H - 1);
    const int wl = max(mw - HALF, 0), wr = min(mw + HALF, W - 1);
    const float lam = (float)HW / ((float)HW - (float)((h2 - h1 + 1) * (wr - wl + 1)));

    const float4* __restrict__ xr = x + (size_t)row * HW4;
    float4* __restrict__ orow = out + (size_t)row * HW4;
    const int t = threadIdx.x;
    const bool tail = (t < 16);

    float4 v0 = xr[t];
    float4 v1 = xr[t + 256];
    float4 v2 = xr[t + 512];
    float4 v3;
    if (tail) v3 = xr[t + 768];

    #define APPLY(v, i4) {                                                \
        const int e  = (i4) << 2;                                         \
        const int hh = e / W;                                             \
        const int ww = e - hh * W;                                        \
        const bool hin = (hh >= h1) & (hh <= h2);                         \
        float4 rr;                                                        \
        rr.x = (hin & (ww     >= wl) & (ww     <= wr)) ? 0.0f : v.x * lam; \
        rr.y = (hin & (ww + 1 >= wl) & (ww + 1 <= wr)) ? 0.0f : v.y * lam; \
        rr.z = (hin & (ww + 2 >= wl) & (ww + 2 <= wr)) ? 0.0f : v.z * lam; \
        rr.w = (hin & (ww + 3 >= wl) & (ww + 3 <= wr)) ? 0.0f : v.w * lam; \
        __stcs(orow + (i4), rr);                                          \
    }

    APPLY(v0, t);
    APPLY(v1, t + 256);
    APPLY(v2, t + 512);
    if (tail) APPLY(v3, t + 768);
    #undef APPLY
}

// ---------------------------------------------------------------------------
extern "C" void kernel_launch(void* const* d_in, const int* in_sizes, int n_in,
                              void* d_out, int out_size)
{
    const float4* x  = (const float4*)d_in[0];
    const float*  w1 = (const float*)d_in[1];
    const float*  w2 = (const float*)d_in[2];
    float4* out = (float4*)d_out;

    void* cnt_ptr = nullptr;
    cudaGetSymbolAddress(&cnt_ptr, g_cnt);
    cudaMemsetAsync(cnt_ptr, 0, B * sizeof(int), 0);

    k1_pool_amax_copy_se<<<NROWS, 256>>>(x, out, w1, w2);
    k3_apply<<<NSEL, 256>>>(x, out);
}